// round 7
// baseline (speedup 1.0000x reference)
#include <cuda_runtime.h>
#include <cstdint>

// KatiesDecoder: out[b, v, u*128:(u+1)*128] = z_prime[b, index[v,u], :]
// z_prime (4, 40962, 128) f32; index (163842, 3) int32; x_ancil unused.
// Output: (4, 163842, 384) f32.
//
// Final structure (158.75 us ncu, pinned at ~6.55 TB/s DRAM = write ceiling;
// traffic at the 1.04 GB floor): one warp per (b, v), 3 independent gathered
// LDG.128 (MLP_p1=3, L2-resident source) + 3 contiguous streaming STG.128
// (__stcs protects the 84 MB z_prime set in L2). R7: pure-uint32 addressing
// (all offsets < 2^32 bytes) to kill 64-bit IMAD chains.

static constexpr int B  = 4;
static constexpr int ND = 40962;   // n_dual
static constexpr int D  = 128;     // d_lat
static constexpr int V  = 163842;  // n_vertex = 6 * 27307
static constexpr int NU = 3;
static constexpr int VEC = D / 4;  // 32 float4 per latent row

static constexpr int Z_ELEMS   = B * ND * D;  // 20,972,544
static constexpr int IDX_ELEMS = V * NU;      // 491,526

static constexpr int WARPS_PER_BLOCK = 6;     // 163842 % 6 == 0 -> exact tiling
static constexpr int THREADS = WARPS_PER_BLOCK * 32;   // 192
static constexpr int GRID_X  = V / WARPS_PER_BLOCK;    // 27307, exact

__global__ void __launch_bounds__(THREADS)
katies_gather_kernel(const float4* __restrict__ z,   // (B, ND, 32) float4
                     const int* __restrict__ idx,    // (V, NU) int32
                     float4* __restrict__ out)       // (B, V, 96) float4
{
    const unsigned v    = blockIdx.x * WARPS_PER_BLOCK + (threadIdx.x >> 5);
    const unsigned b    = blockIdx.y;
    const unsigned lane = threadIdx.x & 31;

    // 3 broadcast index loads (independent).
    const int* ip = idx + v * NU;
    const unsigned j0 = (unsigned)__ldg(ip + 0);
    const unsigned j1 = (unsigned)__ldg(ip + 1);
    const unsigned j2 = (unsigned)__ldg(ip + 2);

    // 3 independent gathered row reads (mostly L2 hits: 21 MB/batch slice).
    // Max element index: 4*40962*32 ~= 5.24M -> uint32 safe.
    const float4* zb = z + b * (unsigned)(ND * VEC) + lane;
    const float4 a0 = __ldg(zb + j0 * (unsigned)VEC);
    const float4 a1 = __ldg(zb + j1 * (unsigned)VEC);
    const float4 a2 = __ldg(zb + j2 * (unsigned)VEC);

    // One contiguous 1536 B destination span per warp.
    // Max element index: 4*163842*96 ~= 62.9M -> uint32 safe.
    float4* dst = out + (b * (unsigned)V + v) * (unsigned)(NU * VEC) + lane;
    __stcs(dst,           a0);
    __stcs(dst +     VEC, a1);
    __stcs(dst + 2 * VEC, a2);
}

extern "C" void kernel_launch(void* const* d_in, const int* in_sizes, int n_in,
                              void* d_out, int out_size)
{
    // Bind inputs by element count (robust to ordering surprises).
    const void* z_ptr   = d_in[0];
    const void* idx_ptr = d_in[2];
    for (int i = 0; i < n_in; i++) {
        if (in_sizes[i] == Z_ELEMS)   z_ptr   = d_in[i];
        if (in_sizes[i] == IDX_ELEMS) idx_ptr = d_in[i];
    }

    const float4* z   = (const float4*)z_ptr;
    const int*    idx = (const int*)idx_ptr;
    float4*       out = (float4*)d_out;

    dim3 grid(GRID_X, B);
    katies_gather_kernel<<<grid, THREADS>>>(z, idx, out);
}

// round 8
// speedup vs baseline: 1.0232x; 1.0232x over previous
#include <cuda_runtime.h>
#include <cstdint>

// KatiesDecoder: out[b, v, u*128:(u+1)*128] = z_prime[b, index[v,u], :]
// z_prime (4, 40962, 128) f32; index (163842, 3) int32; x_ancil unused.
// Output: (4, 163842, 384) f32.
//
// FINAL (roofline-pinned): one warp per (b, v); 3 independent gathered LDG.128
// (MLP_p1=3, source L2-resident at 21 MB/batch) + 3 contiguous streaming
// STG.128 (__stcs protects z_prime in L2 from the 1.007 GB output stream).
// Measured: 158.75 us ncu / 160.3 us bench, DRAM 82.7% (6.55 TB/s) with total
// traffic at the 1.04 GB floor -> time floor ~159 us. Variants tested and
// rejected: MLP=6 pairing (+5 us), 2-vertex interleave (+6 us), 192-thread
// exact tiling (neutral), uint32 addressing (neutral/+2 us).

static constexpr int B  = 4;
static constexpr int ND = 40962;   // n_dual
static constexpr int D  = 128;     // d_lat
static constexpr int V  = 163842;  // n_vertex
static constexpr int NU = 3;
static constexpr int VEC = D / 4;  // 32 float4 per latent row

static constexpr int Z_ELEMS   = B * ND * D;  // 20,972,544
static constexpr int IDX_ELEMS = V * NU;      // 491,526

static constexpr int WARPS_PER_BLOCK = 8;
static constexpr int THREADS = WARPS_PER_BLOCK * 32;

__global__ void __launch_bounds__(THREADS)
katies_gather_kernel(const float4* __restrict__ z,   // (B, ND, 32) float4
                     const int* __restrict__ idx,    // (V, NU) int32
                     float4* __restrict__ out)       // (B, V, 96) float4
{
    const int v = blockIdx.x * WARPS_PER_BLOCK + (threadIdx.x >> 5);
    if (v >= V) return;
    const int b = blockIdx.y;
    const int lane = threadIdx.x & 31;

    // 3 broadcast index loads (independent of each other).
    const int* ip = idx + v * NU;
    const int j0 = __ldg(ip + 0);
    const int j1 = __ldg(ip + 1);
    const int j2 = __ldg(ip + 2);

    // 3 independent gathered row reads (mostly L2 hits).
    const float4* zb = z + (long long)b * ND * VEC;
    const float4 a0 = __ldg(zb + (long long)j0 * VEC + lane);
    const float4 a1 = __ldg(zb + (long long)j1 * VEC + lane);
    const float4 a2 = __ldg(zb + (long long)j2 * VEC + lane);

    // One contiguous 1536 B destination span per warp.
    float4* dst = out + ((long long)b * V + v) * (NU * VEC) + lane;
    __stcs(dst,           a0);
    __stcs(dst +     VEC, a1);
    __stcs(dst + 2 * VEC, a2);
}

extern "C" void kernel_launch(void* const* d_in, const int* in_sizes, int n_in,
                              void* d_out, int out_size)
{
    // Bind inputs by element count (robust to ordering surprises).
    const void* z_ptr   = d_in[0];
    const void* idx_ptr = d_in[2];
    for (int i = 0; i < n_in; i++) {
        if (in_sizes[i] == Z_ELEMS)   z_ptr   = d_in[i];
        if (in_sizes[i] == IDX_ELEMS) idx_ptr = d_in[i];
    }

    const float4* z   = (const float4*)z_ptr;
    const int*    idx = (const int*)idx_ptr;
    float4*       out = (float4*)d_out;

    dim3 grid((V + WARPS_PER_BLOCK - 1) / WARPS_PER_BLOCK, B);
    katies_gather_kernel<<<grid, THREADS>>>(z, idx, out);
}